// round 8
// baseline (speedup 1.0000x reference)
#include <cuda_runtime.h>
#include <cstdint>
#include <cstddef>

typedef unsigned long long ull;

#define S_LEN 512
#define B_SZ  256
#define D_SZ  128
#define R_SZ  2048

__device__ float  g_hist[(size_t)S_LEN * B_SZ * R_SZ];
__device__ double g_pc_part[8];
__device__ double g_mse_part[128];

__device__ __forceinline__ ull pk2(float lo, float hi) {
    ull r; asm("mov.b64 %0, {%1,%2};" : "=l"(r) : "f"(lo), "f"(hi)); return r;
}
__device__ __forceinline__ void upk2(float& lo, float& hi, ull v) {
    asm("mov.b64 {%0,%1}, %2;" : "=f"(lo), "=f"(hi) : "l"(v));
}
__device__ __forceinline__ ull fma2(ull a, ull b, ull c) {
    ull d; asm("fma.rn.f32x2 %0, %1, %2, %3;" : "=l"(d) : "l"(a), "l"(b), "l"(c)); return d;
}
__device__ __forceinline__ float clip5(float v) { return fminf(fmaxf(v, -5.f), 5.f); }

// XLA:GPU-style contracted oscillator step (LLVM DAG-combine fma placement):
//   gy    = (2|gamma|) * y                        (separate mul)
//   accel = fma(-w2, x, fma(a, f, -gy))           (lhs muls fused)
//   x'    = clip(fma(H, y, x))
//   y'    = clip(fma(H, accel, y))
__device__ __forceinline__ float osc_upd(float f, float& x, float& y,
                                         float a, float g2, float w2) {
    float gy = __fmul_rn(g2, y);
    float ac = fmaf(-w2, x, fmaf(a, f, -gy));
    float xn = clip5(fmaf(0.5f, y, x));
    float yn = clip5(fmaf(0.5f, ac, y));
    x = xn; y = yn;
    return xn;
}

// ============ Phase A: persistent recurrence ============
__global__ void __launch_bounds__(256, 1) phaseA_kernel(
    const float* __restrict__ inputs,
    const float* __restrict__ om_in, const float* __restrict__ ga_in, const float* __restrict__ al_in,
    const float* __restrict__ Wp,    const float* __restrict__ bp,
    const float* __restrict__ om_r,  const float* __restrict__ ga_r,  const float* __restrict__ al_r,
    const float* __restrict__ om_o,  const float* __restrict__ ga_o,  const float* __restrict__ al_o)
{
    const int cb  = blockIdx.x;   // 0..15 reservoir col block
    const int rb  = blockIdx.y;   // 0..7  batch row block
    const int tid = threadIdx.x;

    extern __shared__ float smem[];
    float* wt = smem;                       // [128 d][128 c]
    ull*   xd = (ull*)(smem + 128 * 128);   // [32 row][128 d] duplicated x_in

    __shared__ float  pa[128], pg[128], pw[128];
    __shared__ double redd[256];

    for (int i = tid; i < 4096; i += 256) {
        int c = i >> 5, d0 = (i & 31) << 2;
        float4 v = *(const float4*)(Wp + ((size_t)(cb * 128 + c)) * D_SZ + d0);
        wt[(d0+0)*128 + c] = v.x; wt[(d0+1)*128 + c] = v.y;
        wt[(d0+2)*128 + c] = v.z; wt[(d0+3)*128 + c] = v.w;
    }
    if (tid < 128) {
        pa[tid] = al_in[tid];
        pg[tid] = __fmul_rn(2.f, fabsf(ga_in[tid]));
        float o = fabsf(om_in[tid]); pw[tid] = __fmul_rn(o, o);
    }

    const int irow = tid >> 3;
    const int dch  = (tid & 7) << 4;
    const int gb_i = rb * 32 + irow;

    const int lane = tid & 31, warp = tid >> 5;
    const int r0 = (lane & 7) << 2;
    const int c0 = warp * 16 + ((lane >> 3) << 2);

    float par[4], pgr[4], pwr[4], pao[4], pgo[4], pwo[4], bpv[4];
    {
        int rbase = cb * 128 + c0;
        #pragma unroll
        for (int j = 0; j < 4; ++j) {
            par[j] = al_r[rbase+j];
            pgr[j] = __fmul_rn(2.f, fabsf(ga_r[rbase+j]));
            float o = fabsf(om_r[rbase+j]); pwr[j] = __fmul_rn(o, o);
            pao[j] = al_o[rbase+j];
            pgo[j] = __fmul_rn(2.f, fabsf(ga_o[rbase+j]));
            float q = fabsf(om_o[rbase+j]); pwo[j] = __fmul_rn(q, q);
            bpv[j] = bp[rbase+j];
        }
    }

    float x_in[16], y_in[16], xr[16], yr[16], xo[16], yo[16];
    #pragma unroll
    for (int k = 0; k < 16; ++k) { x_in[k]=0.f; y_in[k]=0.f; xr[k]=0.f; yr[k]=0.f; xo[k]=0.f; yo[k]=0.f; }

    double lin = 0.0, lmse = 0.0;

    float inpv[16];
    {
        const float* p = inputs + (size_t)gb_i * (S_LEN * D_SZ) + dch;
        #pragma unroll
        for (int q = 0; q < 4; ++q) {
            float4 v = *(const float4*)(p + q*4);
            inpv[q*4]=v.x; inpv[q*4+1]=v.y; inpv[q*4+2]=v.z; inpv[q*4+3]=v.w;
        }
    }
    __syncthreads();   // staging (wt, pa/pg/pw) complete before any use

    for (int t = 0; t < S_LEN; ++t) {
        if (t > 0) {
            float ls = 0.f;
            #pragma unroll
            for (int k = 0; k < 16; ++k) { float df = x_in[k]-inpv[k]; ls = fmaf(df, df, ls); }
            lin += (double)ls;
        }
        #pragma unroll
        for (int k = 0; k < 16; ++k) {
            int d = dch + k;
            osc_upd(inpv[k], x_in[k], y_in[k], pa[d], pg[d], pw[d]);
        }
        __syncthreads();   // prev step's GEMM readers done with xd
        #pragma unroll
        for (int k = 0; k < 16; ++k)
            xd[irow * 128 + dch + k] = pk2(x_in[k], x_in[k]);
        __syncthreads();

        {   // prefetch next input slice under the GEMM
            int tn = (t < S_LEN-1) ? t+1 : t;
            const float* p = inputs + (size_t)gb_i * (S_LEN*D_SZ) + (size_t)tn * D_SZ + dch;
            #pragma unroll
            for (int q = 0; q < 4; ++q) {
                float4 v = *(const float4*)(p + q*4);
                inpv[q*4]=v.x; inpv[q*4+1]=v.y; inpv[q*4+2]=v.z; inpv[q*4+3]=v.w;
            }
        }

        // GEMM1 tile: proj = x_in @ Wp^T  (fp32, acc from 0, ascending d, +bias after)
        ull acc[8];
        #pragma unroll
        for (int i = 0; i < 8; ++i) acc[i] = 0ull;
        #pragma unroll 8
        for (int d = 0; d < 128; d += 2) {
            ulonglong2 w0 = *(const ulonglong2*)(wt + d*128 + c0);
            ulonglong2 w1 = *(const ulonglong2*)(wt + (d+1)*128 + c0);
            #pragma unroll
            for (int i = 0; i < 4; ++i) {
                ulonglong2 xv = *(const ulonglong2*)(xd + (r0+i)*128 + d);
                acc[2*i]   = fma2(xv.x, w0.x, acc[2*i]);
                acc[2*i+1] = fma2(xv.x, w0.y, acc[2*i+1]);
                acc[2*i]   = fma2(xv.y, w1.x, acc[2*i]);
                acc[2*i+1] = fma2(xv.y, w1.y, acc[2*i+1]);
            }
        }

        float ls2 = 0.f;
        #pragma unroll
        for (int i = 0; i < 4; ++i) {
            #pragma unroll
            for (int p = 0; p < 2; ++p) {
                float f0, f1; upk2(f0, f1, acc[2*i+p]);
                #pragma unroll
                for (int h = 0; h < 2; ++h) {
                    int j = 2*p + h, k = i*4 + j;
                    float fv = __fadd_rn(h ? f1 : f0, bpv[j]);
                    float xrn = osc_upd(fv,  xr[k], yr[k], par[j], pgr[j], pwr[j]);
                    float xon = osc_upd(xrn, xo[k], yo[k], pao[j], pgo[j], pwo[j]);
                    float df = xon - xrn;
                    ls2 = fmaf(df, df, ls2);
                }
            }
        }
        lmse += (double)ls2;

        size_t hb = ((size_t)t * B_SZ + rb*32 + r0) * R_SZ + cb*128 + c0;
        #pragma unroll
        for (int i = 0; i < 4; ++i)
            *(float4*)(g_hist + hb + (size_t)i * R_SZ) =
                make_float4(xo[i*4], xo[i*4+1], xo[i*4+2], xo[i*4+3]);
    }

    __syncthreads();
    redd[tid] = lin; __syncthreads();
    for (int s = 128; s > 0; s >>= 1) { if (tid < s) redd[tid] += redd[tid+s]; __syncthreads(); }
    if (tid == 0 && cb == 0) g_pc_part[rb] = redd[0];
    __syncthreads();
    redd[tid] = lmse; __syncthreads();
    for (int s = 128; s > 0; s >>= 1) { if (tid < s) redd[tid] += redd[tid+s]; __syncthreads(); }
    if (tid == 0) g_mse_part[rb*16 + cb] = redd[0];
}

// ============ Phase B: preds = hist @ W_read^T + b_read ============
__global__ void __launch_bounds__(256, 2) gemm2_kernel(
    const float* __restrict__ Wr, const float* __restrict__ brd, float* __restrict__ out)
{
    __shared__ __align__(16) float ws[32 * 128];   // ws[k][c]
    __shared__ __align__(16) float as[64 * 33];    // as[r][k], pitch 33

    const int tid = threadIdx.x;
    const int tx = tid & 15, ty = tid >> 4;
    const int c0 = tx * 8, r0 = ty * 4;
    const size_t mBase = (size_t)blockIdx.x * 64;

    ull acc[16];
    #pragma unroll
    for (int i = 0; i < 16; ++i) acc[i] = 0ull;

    for (int kc = 0; kc < R_SZ; kc += 32) {
        __syncthreads();
        for (int i = tid; i < 1024; i += 256) {
            int c = i >> 3, kk = (i & 7) << 2;
            float4 v = *(const float4*)(Wr + (size_t)c * R_SZ + kc + kk);
            ws[(kk+0)*128 + c] = v.x; ws[(kk+1)*128 + c] = v.y;
            ws[(kk+2)*128 + c] = v.z; ws[(kk+3)*128 + c] = v.w;
        }
        for (int i = tid; i < 512; i += 256) {
            int r = i >> 3, kk = (i & 7) << 2;
            float4 v = *(const float4*)(g_hist + (mBase + r) * R_SZ + kc + kk);
            as[r*33 + kk]   = v.x; as[r*33 + kk+1] = v.y;
            as[r*33 + kk+2] = v.z; as[r*33 + kk+3] = v.w;
        }
        __syncthreads();

        #pragma unroll 8
        for (int k = 0; k < 32; ++k) {
            ulonglong2 w0 = *(const ulonglong2*)(ws + k*128 + c0);
            ulonglong2 w1 = *(const ulonglong2*)(ws + k*128 + c0 + 4);
            #pragma unroll
            for (int i = 0; i < 4; ++i) {
                float av = as[(r0+i)*33 + k];
                ull a2 = pk2(av, av);
                acc[i*4+0] = fma2(a2, w0.x, acc[i*4+0]);
                acc[i*4+1] = fma2(a2, w0.y, acc[i*4+1]);
                acc[i*4+2] = fma2(a2, w1.x, acc[i*4+2]);
                acc[i*4+3] = fma2(a2, w1.y, acc[i*4+3]);
            }
        }
    }

    #pragma unroll
    for (int i = 0; i < 4; ++i) {
        size_t m = mBase + r0 + i;
        int b = (int)(m & 255), t = (int)(m >> 8);
        float* o = out + (size_t)b * (S_LEN * D_SZ) + (size_t)t * D_SZ + c0;
        float v[8];
        #pragma unroll
        for (int q = 0; q < 4; ++q) upk2(v[2*q], v[2*q+1], acc[i*4+q]);
        #pragma unroll
        for (int q = 0; q < 8; ++q) v[q] = __fadd_rn(v[q], brd[c0 + q]);
        *(float4*)(o)     = make_float4(v[0], v[1], v[2], v[3]);
        *(float4*)(o + 4) = make_float4(v[4], v[5], v[6], v[7]);
    }
}

// ============ Final loss reduce ============
__global__ void reduce_kernel(float* __restrict__ out, int out_size)
{
    if (threadIdx.x != 0 || blockIdx.x != 0) return;
    double a = 0.0, b = 0.0;
    for (int i = 0; i < 8; ++i)   a += g_pc_part[i];
    for (int i = 0; i < 128; ++i) b += g_mse_part[i];
    a /= (double)(B_SZ * D_SZ);
    b /= (double)(B_SZ * R_SZ);
    size_t base = (size_t)B_SZ * S_LEN * D_SZ;
    if ((size_t)out_size >= base + 2) {
        out[base]     = (float)a;
        out[base + 1] = (float)b;
    }
}

extern "C" void kernel_launch(void* const* d_in, const int* in_sizes, int n_in,
                              void* d_out, int out_size)
{
    const float* inputs = (const float*)d_in[0];
    const float* om_in  = (const float*)d_in[1];
    const float* ga_in  = (const float*)d_in[2];
    const float* al_in  = (const float*)d_in[3];
    const float* Wp     = (const float*)d_in[4];
    const float* bp     = (const float*)d_in[5];
    const float* om_r   = (const float*)d_in[6];
    const float* ga_r   = (const float*)d_in[7];
    const float* al_r   = (const float*)d_in[8];
    const float* om_o   = (const float*)d_in[9];
    const float* ga_o   = (const float*)d_in[10];
    const float* al_o   = (const float*)d_in[11];
    const float* Wr     = (const float*)d_in[12];
    const float* brd    = (const float*)d_in[13];
    float* out = (float*)d_out;

    cudaFuncSetAttribute(phaseA_kernel,
        cudaFuncAttributeMaxDynamicSharedMemorySize, 98304);

    dim3 gA(16, 8);
    phaseA_kernel<<<gA, 256, 98304>>>(inputs, om_in, ga_in, al_in, Wp, bp,
                                      om_r, ga_r, al_r, om_o, ga_o, al_o);
    gemm2_kernel<<<2048, 256>>>(Wr, brd, out);
    reduce_kernel<<<1, 1>>>(out, out_size);
}

// round 9
// speedup vs baseline: 3.9560x; 3.9560x over previous
#include <cuda_runtime.h>
#include <cstdint>
#include <cstddef>

typedef unsigned long long ull;

#define S_LEN 512
#define B_SZ  256
#define D_SZ  128
#define R_SZ  2048

__device__ float  g_hist[(size_t)S_LEN * B_SZ * R_SZ];
__device__ double g_pc_part[8];
__device__ double g_mse_part[128];

__device__ __forceinline__ ull pk2(float lo, float hi) {
    ull r; asm("mov.b64 %0, {%1,%2};" : "=l"(r) : "f"(lo), "f"(hi)); return r;
}
__device__ __forceinline__ void upk2(float& lo, float& hi, ull v) {
    asm("mov.b64 {%0,%1}, %2;" : "=f"(lo), "=f"(hi) : "l"(v));
}
__device__ __forceinline__ ull fma2(ull a, ull b, ull c) {
    ull d; asm("fma.rn.f32x2 %0, %1, %2, %3;" : "=l"(d) : "l"(a), "l"(b), "l"(c)); return d;
}
__device__ __forceinline__ float clip5(float v) { return fminf(fmaxf(v, -5.f), 5.f); }

// XLA:GPU-contracted oscillator step (matched recipe — DO NOT CHANGE)
__device__ __forceinline__ float osc_upd(float f, float& x, float& y,
                                         float a, float g2, float w2) {
    float gy = __fmul_rn(g2, y);
    float ac = fmaf(-w2, x, fmaf(a, f, -gy));
    float xn = clip5(fmaf(0.5f, y, x));
    float yn = clip5(fmaf(0.5f, ac, y));
    x = xn; y = yn;
    return xn;
}

// ============ Phase A: persistent recurrence ============
// Grid (16 col-blocks, 8 row-blocks), 256 threads.
// smem: wt[128 d][128 c] (64KB) + xs[128 d][32 rows] (16KB)
__global__ void __launch_bounds__(256, 1) phaseA_kernel(
    const float* __restrict__ inputs,
    const float* __restrict__ om_in, const float* __restrict__ ga_in, const float* __restrict__ al_in,
    const float* __restrict__ Wp,    const float* __restrict__ bp,
    const float* __restrict__ om_r,  const float* __restrict__ ga_r,  const float* __restrict__ al_r,
    const float* __restrict__ om_o,  const float* __restrict__ ga_o,  const float* __restrict__ al_o)
{
    const int cb  = blockIdx.x;   // 0..15 reservoir col block
    const int rb  = blockIdx.y;   // 0..7  batch row block
    const int tid = threadIdx.x;

    extern __shared__ float smem[];
    float* wt = smem;                 // [128 d][128 c]
    float* xs = smem + 128 * 128;     // [128 d][32 rows] (plain, 128B rows)

    __shared__ float  pa[128], pg[128], pw[128];
    __shared__ double redd[256];

    // stage W_proj tile transposed: wt[d][c] = Wp[cb*128+c][d]
    for (int i = tid; i < 4096; i += 256) {
        int c = i >> 5, d0 = (i & 31) << 2;
        float4 v = *(const float4*)(Wp + ((size_t)(cb * 128 + c)) * D_SZ + d0);
        wt[(d0+0)*128 + c] = v.x; wt[(d0+1)*128 + c] = v.y;
        wt[(d0+2)*128 + c] = v.z; wt[(d0+3)*128 + c] = v.w;
    }
    if (tid < 128) {
        pa[tid] = al_in[tid];
        pg[tid] = __fmul_rn(2.f, fabsf(ga_in[tid]));
        float o = fabsf(om_in[tid]); pw[tid] = __fmul_rn(o, o);
    }

    // input-oscillator mapping: row = lane, 16 consecutive d per warp
    const int irow = tid & 31;            // 0..31
    const int dch  = (tid >> 5) << 4;     // warp*16
    const int gb_i = rb * 32 + irow;

    // GEMM mapping: 4 rows x 4 cols per thread (row-pair f32x2 packing)
    const int lane = tid & 31, warp = tid >> 5;
    const int r0 = (lane & 7) << 2;
    const int c0 = warp * 16 + ((lane >> 3) << 2);

    float par[4], pgr[4], pwr[4], pao[4], pgo[4], pwo[4], bpv[4];
    {
        int rbase = cb * 128 + c0;
        #pragma unroll
        for (int j = 0; j < 4; ++j) {
            par[j] = al_r[rbase+j];
            pgr[j] = __fmul_rn(2.f, fabsf(ga_r[rbase+j]));
            float o = fabsf(om_r[rbase+j]); pwr[j] = __fmul_rn(o, o);
            pao[j] = al_o[rbase+j];
            pgo[j] = __fmul_rn(2.f, fabsf(ga_o[rbase+j]));
            float q = fabsf(om_o[rbase+j]); pwo[j] = __fmul_rn(q, q);
            bpv[j] = bp[rbase+j];
        }
    }

    float x_in[16], y_in[16], xr[16], yr[16], xo[16], yo[16];
    #pragma unroll
    for (int k = 0; k < 16; ++k) { x_in[k]=0.f; y_in[k]=0.f; xr[k]=0.f; yr[k]=0.f; xo[k]=0.f; yo[k]=0.f; }

    double lin = 0.0, lmse = 0.0;

    float inpv[16];
    {
        const float* p = inputs + (size_t)gb_i * (S_LEN * D_SZ) + dch;
        #pragma unroll
        for (int q = 0; q < 4; ++q) {
            float4 v = *(const float4*)(p + q*4);
            inpv[q*4]=v.x; inpv[q*4+1]=v.y; inpv[q*4+2]=v.z; inpv[q*4+3]=v.w;
        }
    }
    __syncthreads();   // staging complete before any use

    for (int t = 0; t < S_LEN; ++t) {
        if (t > 0) {
            float ls = 0.f;
            #pragma unroll
            for (int k = 0; k < 16; ++k) { float df = x_in[k]-inpv[k]; ls = fmaf(df, df, ls); }
            lin += (double)ls;
        }
        #pragma unroll
        for (int k = 0; k < 16; ++k) {
            int d = dch + k;
            osc_upd(inpv[k], x_in[k], y_in[k], pa[d], pg[d], pw[d]);
        }
        __syncthreads();   // prev step's GEMM readers done with xs
        #pragma unroll
        for (int k = 0; k < 16; ++k)
            xs[(dch + k) * 32 + irow] = x_in[k];   // conflict-free (lanes = consecutive rows)
        __syncthreads();

        {   // prefetch next input slice under the GEMM
            int tn = (t < S_LEN-1) ? t+1 : t;
            const float* p = inputs + (size_t)gb_i * (S_LEN*D_SZ) + (size_t)tn * D_SZ + dch;
            #pragma unroll
            for (int q = 0; q < 4; ++q) {
                float4 v = *(const float4*)(p + q*4);
                inpv[q*4]=v.x; inpv[q*4+1]=v.y; inpv[q*4+2]=v.z; inpv[q*4+3]=v.w;
            }
        }

        // GEMM1 tile: proj = x_in @ Wp^T
        // acc[rp][j] packs rows (r0+2rp, r0+2rp+1) for col c0+j.
        // Per element: acc=0, ascending-d fma chain — identical math to R8.
        ull acc[2][4];
        #pragma unroll
        for (int j = 0; j < 4; ++j) { acc[0][j] = 0ull; acc[1][j] = 0ull; }

        #pragma unroll 8
        for (int d = 0; d < 128; d += 2) {
            float4 xa = *(const float4*)(xs + d*32 + r0);        // rows r0..r0+3 @ d
            float4 xb = *(const float4*)(xs + (d+1)*32 + r0);    // rows r0..r0+3 @ d+1
            float4 wa = *(const float4*)(wt + d*128 + c0);       // cols c0..c0+3 @ d
            float4 wb = *(const float4*)(wt + (d+1)*128 + c0);
            ull xa0 = pk2(xa.x, xa.y), xa1 = pk2(xa.z, xa.w);
            ull xb0 = pk2(xb.x, xb.y), xb1 = pk2(xb.z, xb.w);
            float wav[4] = {wa.x, wa.y, wa.z, wa.w};
            float wbv[4] = {wb.x, wb.y, wb.z, wb.w};
            #pragma unroll
            for (int j = 0; j < 4; ++j) {
                ull wda = pk2(wav[j], wav[j]);
                ull wdb = pk2(wbv[j], wbv[j]);
                acc[0][j] = fma2(xa0, wda, acc[0][j]);
                acc[1][j] = fma2(xa1, wda, acc[1][j]);
                acc[0][j] = fma2(xb0, wdb, acc[0][j]);
                acc[1][j] = fma2(xb1, wdb, acc[1][j]);
            }
        }

        // unpack: element (i row, j col), i = 2*rp + half
        float fv[4][4];
        #pragma unroll
        for (int rp = 0; rp < 2; ++rp)
            #pragma unroll
            for (int j = 0; j < 4; ++j) {
                float lo, hi; upk2(lo, hi, acc[rp][j]);
                fv[2*rp][j] = lo; fv[2*rp+1][j] = hi;
            }

        float ls2 = 0.f;
        #pragma unroll
        for (int i = 0; i < 4; ++i) {
            #pragma unroll
            for (int j = 0; j < 4; ++j) {
                int k = i*4 + j;
                float f = __fadd_rn(fv[i][j], bpv[j]);   // bias after dot (matched)
                float xrn = osc_upd(f,   xr[k], yr[k], par[j], pgr[j], pwr[j]);
                float xon = osc_upd(xrn, xo[k], yo[k], pao[j], pgo[j], pwo[j]);
                float df = xon - xrn;
                ls2 = fmaf(df, df, ls2);
            }
        }
        lmse += (double)ls2;

        size_t hb = ((size_t)t * B_SZ + rb*32 + r0) * R_SZ + cb*128 + c0;
        #pragma unroll
        for (int i = 0; i < 4; ++i)
            *(float4*)(g_hist + hb + (size_t)i * R_SZ) =
                make_float4(xo[i*4], xo[i*4+1], xo[i*4+2], xo[i*4+3]);
    }

    __syncthreads();
    redd[tid] = lin; __syncthreads();
    for (int s = 128; s > 0; s >>= 1) { if (tid < s) redd[tid] += redd[tid+s]; __syncthreads(); }
    if (tid == 0 && cb == 0) g_pc_part[rb] = redd[0];
    __syncthreads();
    redd[tid] = lmse; __syncthreads();
    for (int s = 128; s > 0; s >>= 1) { if (tid < s) redd[tid] += redd[tid+s]; __syncthreads(); }
    if (tid == 0) g_mse_part[rb*16 + cb] = redd[0];
}

// ============ Phase B: preds = hist @ W_read^T + b_read ============
#define WS_PITCH 132   // floats; 528B rows: 16B-aligned, staging conflict ~2-way, inner conflict-free
__global__ void __launch_bounds__(256, 2) gemm2_kernel(
    const float* __restrict__ Wr, const float* __restrict__ brd, float* __restrict__ out)
{
    __shared__ __align__(16) float ws[32 * WS_PITCH];   // ws[k][c]
    __shared__ __align__(16) float as[64 * 33];         // as[r][k], pitch 33

    const int tid = threadIdx.x;
    const int tx = tid & 15, ty = tid >> 4;
    const int c0 = tx * 8, r0 = ty * 4;
    const size_t mBase = (size_t)blockIdx.x * 64;

    ull acc[16];
    #pragma unroll
    for (int i = 0; i < 16; ++i) acc[i] = 0ull;

    for (int kc = 0; kc < R_SZ; kc += 32) {
        __syncthreads();
        for (int i = tid; i < 1024; i += 256) {
            int c = i >> 3, kk = (i & 7) << 2;
            float4 v = *(const float4*)(Wr + (size_t)c * R_SZ + kc + kk);
            ws[(kk+0)*WS_PITCH + c] = v.x; ws[(kk+1)*WS_PITCH + c] = v.y;
            ws[(kk+2)*WS_PITCH + c] = v.z; ws[(kk+3)*WS_PITCH + c] = v.w;
        }
        for (int i = tid; i < 512; i += 256) {
            int r = i >> 3, kk = (i & 7) << 2;
            float4 v = *(const float4*)(g_hist + (mBase + r) * R_SZ + kc + kk);
            as[r*33 + kk]   = v.x; as[r*33 + kk+1] = v.y;
            as[r*33 + kk+2] = v.z; as[r*33 + kk+3] = v.w;
        }
        __syncthreads();

        #pragma unroll 8
        for (int k = 0; k < 32; ++k) {
            ulonglong2 w0 = *(const ulonglong2*)(ws + k*WS_PITCH + c0);
            ulonglong2 w1 = *(const ulonglong2*)(ws + k*WS_PITCH + c0 + 4);
            #pragma unroll
            for (int i = 0; i < 4; ++i) {
                float av = as[(r0+i)*33 + k];
                ull a2 = pk2(av, av);
                acc[i*4+0] = fma2(a2, w0.x, acc[i*4+0]);
                acc[i*4+1] = fma2(a2, w0.y, acc[i*4+1]);
                acc[i*4+2] = fma2(a2, w1.x, acc[i*4+2]);
                acc[i*4+3] = fma2(a2, w1.y, acc[i*4+3]);
            }
        }
    }

    #pragma unroll
    for (int i = 0; i < 4; ++i) {
        size_t m = mBase + r0 + i;
        int b = (int)(m & 255), t = (int)(m >> 8);
        float* o = out + (size_t)b * (S_LEN * D_SZ) + (size_t)t * D_SZ + c0;
        float v[8];
        #pragma unroll
        for (int q = 0; q < 4; ++q) upk2(v[2*q], v[2*q+1], acc[i*4+q]);
        #pragma unroll
        for (int q = 0; q < 8; ++q) v[q] = __fadd_rn(v[q], brd[c0 + q]);
        *(float4*)(o)     = make_float4(v[0], v[1], v[2], v[3]);
        *(float4*)(o + 4) = make_float4(v[4], v[5], v[6], v[7]);
    }
}

// ============ Final loss reduce ============
__global__ void reduce_kernel(float* __restrict__ out, int out_size)
{
    if (threadIdx.x != 0 || blockIdx.x != 0) return;
    double a = 0.0, b = 0.0;
    for (int i = 0; i < 8; ++i)   a += g_pc_part[i];
    for (int i = 0; i < 128; ++i) b += g_mse_part[i];
    a /= (double)(B_SZ * D_SZ);
    b /= (double)(B_SZ * R_SZ);
    size_t base = (size_t)B_SZ * S_LEN * D_SZ;
    if ((size_t)out_size >= base + 2) {
        out[base]     = (float)a;
        out[base + 1] = (float)b;
    }
}

extern "C" void kernel_launch(void* const* d_in, const int* in_sizes, int n_in,
                              void* d_out, int out_size)
{
    const float* inputs = (const float*)d_in[0];
    const float* om_in  = (const float*)d_in[1];
    const float* ga_in  = (const float*)d_in[2];
    const float* al_in  = (const float*)d_in[3];
    const float* Wp     = (const float*)d_in[4];
    const float* bp     = (const float*)d_in[5];
    const float* om_r   = (const float*)d_in[6];
    const float* ga_r   = (const float*)d_in[7];
    const float* al_r   = (const float*)d_in[8];
    const float* om_o   = (const float*)d_in[9];
    const float* ga_o   = (const float*)d_in[10];
    const float* al_o   = (const float*)d_in[11];
    const float* Wr     = (const float*)d_in[12];
    const float* brd    = (const float*)d_in[13];
    float* out = (float*)d_out;

    cudaFuncSetAttribute(phaseA_kernel,
        cudaFuncAttributeMaxDynamicSharedMemorySize, 81920);

    dim3 gA(16, 8);
    phaseA_kernel<<<gA, 256, 81920>>>(inputs, om_in, ga_in, al_in, Wp, bp,
                                      om_r, ga_r, al_r, om_o, ga_o, al_o);
    gemm2_kernel<<<2048, 256>>>(Wr, brd, out);
    reduce_kernel<<<1, 1>>>(out, out_size);
}